// round 5
// baseline (speedup 1.0000x reference)
#include <cuda_runtime.h>
#include <math.h>

// Problem constants
constexpr int kB = 256, kN = 1152, kD = 8, kO = 10, kE = 16;
constexpr int kOE = kO * kE;  // 160

// Tiling: block owns 8 n and HALF the batches (128), in 16 chunks of 8.
constexpr int kNL   = 8;
constexpr int kTH   = 320;        // tid = nl + 8*eg + 32*o  (warp == o)
constexpr int kGX   = kN / kNL;   // 144 n-groups
constexpr int kGY   = 2;          // batch halves
constexpr int kBH   = kB / kGY;   // 128 batches per block
constexpr int kCB   = 8;          // batches per chunk
constexpr int kNCH  = kBH / kCB;  // 16 chunks

// SMEM (floats)
constexpr int kUSd  = kBH;                   // u_s d stride (128)
constexpr int kUSnl = kD * kUSd + 4;         // 1028 (mod 32 = 4: 8 nl tiles banks)
constexpr int kOffA = kNL * kUSnl;           // 8224
constexpr int kAPad = 84;
constexpr int kABuf = kNL * kAPad;           // 672 (double-buffered logits)
constexpr int kSmemFloats = kOffA + 2 * kABuf;  // 9568
constexpr int kSmemBytes  = kSmemFloats * 4;    // 38272

typedef unsigned long long u64;

__device__ float g_part[(size_t)kGX * kB * kOE];  // 23.6 MB
__device__ float g_vsum[kB * kOE];

#define FMA2(d, a, b_) asm("fma.rn.f32x2 %0, %1, %2, %0;" : "+l"(d) : "l"(a), "l"(b_))
#define MUL2(d, a, b_) asm("mul.rn.f32x2 %0, %1, %2;" : "=l"(d) : "l"(a), "l"(b_))
#define ADD2(d, a, b_) asm("add.rn.f32x2 %0, %1, %2;" : "=l"(d) : "l"(a), "l"(b_))
#define PACK2(d, lo, hi) \
  asm("mov.b64 %0, {%1, %2};" : "=l"(d) : "r"(__float_as_uint(lo)), "r"(__float_as_uint(hi)))
#define UNPK2(lo, hi, v)                                                \
  do {                                                                  \
    unsigned _l, _h;                                                    \
    asm("mov.b64 {%0, %1}, %2;" : "=r"(_l), "=r"(_h) : "l"(v));         \
    lo = __uint_as_float(_l); hi = __uint_as_float(_h);                 \
  } while (0)

__global__ void noop_kernel() {}

// MODE 0: c = 0.1.  MODE 1: c = softmax_o(<u_ji, g_vsum>).
template <int MODE>
__global__ void __launch_bounds__(kTH, 2) pass_kernel(
    const float* __restrict__ u_i,
    const float* __restrict__ W,
    const float* __restrict__ bias)
{
  extern __shared__ float sm[];
  float* u_s = sm;                  // [nl(1028)][d(128)][b]
  float* a_s = sm + kOffA;          // 2 x [nl][84] logits (double-buffered)

  const int tid = threadIdx.x;
  const int nl  = tid & 7;
  const int eg  = (tid >> 3) & 3;
  const int o   = tid >> 5;         // warp id
  const int n0  = blockIdx.x * kNL;
  const int bb0 = blockIdx.y * kBH; // this block's batch base

  // ---- W slice into registers (once per pass) ----
  float w[kD][4];
  {
    const float* Wp = W + ((size_t)(n0 + nl) * kO + o) * (kD * kE) + eg * 4;
#pragma unroll
    for (int d = 0; d < kD; d++) {
      float4 w4 = *(const float4*)(Wp + d * kE);
      w[d][0] = w4.x; w[d][1] = w4.y; w[d][2] = w4.z; w[d][3] = w4.w;
    }
  }
  const float bv = bias[(n0 + nl) * kO + o];
  u64 bp; PACK2(bp, bv, bv);

  // ---- stage u once: [b][n][d] -> [nl][d][b_local] ----
  for (int i = tid; i < kBH * kNL * 2; i += kTH) {
    int b = i >> 4, nl2 = (i >> 1) & 7, h = i & 1;
    float4 t = *(const float4*)(u_i + ((size_t)(bb0 + b) * kN + n0 + nl2) * kD + h * 4);
    float* du = u_s + nl2 * kUSnl + h * 4 * kUSd + b;
    du[0] = t.x; du[kUSd] = t.y; du[2 * kUSd] = t.z; du[3 * kUSd] = t.w;
  }
  __syncthreads();

  const float* up_base = u_s + nl * kUSnl;
  const int mm = ((nl >> 2) & 1) * 8 + ((nl >> 1) & 1) * 4 + (nl & 1) * 2;
  const int kk = mm >> 2, j0 = mm & 3;  // this lane's final (batch-pair, e-pair)

  for (int ch = 0; ch < kNCH; ch++) {
    const int bc  = ch * kCB;      // local batch offset
    const int bca = bb0 + bc;      // absolute batch offset
    float* ab = a_s + (ch & 1) * kABuf;

    // ---- u_ji tile (bias included); f32x2 packed over batch pairs ----
    u64 acc[4][4];
#pragma unroll
    for (int k = 0; k < 4; k++)
#pragma unroll
      for (int j = 0; j < 4; j++) acc[k][j] = bp;

    const float* up = up_base + bc;
#pragma unroll
    for (int d = 0; d < kD; d++) {
      ulonglong2 ua = *(const ulonglong2*)(up + d * kUSd);      // b (0,1),(2,3)
      ulonglong2 ub = *(const ulonglong2*)(up + d * kUSd + 4);  // b (4,5),(6,7)
      u64 w2[4];
      PACK2(w2[0], w[d][0], w[d][0]); PACK2(w2[1], w[d][1], w[d][1]);
      PACK2(w2[2], w[d][2], w[d][2]); PACK2(w2[3], w[d][3], w[d][3]);
      FMA2(acc[0][0], ua.x, w2[0]); FMA2(acc[0][1], ua.x, w2[1]);
      FMA2(acc[0][2], ua.x, w2[2]); FMA2(acc[0][3], ua.x, w2[3]);
      FMA2(acc[1][0], ua.y, w2[0]); FMA2(acc[1][1], ua.y, w2[1]);
      FMA2(acc[1][2], ua.y, w2[2]); FMA2(acc[1][3], ua.y, w2[3]);
      FMA2(acc[2][0], ub.x, w2[0]); FMA2(acc[2][1], ub.x, w2[1]);
      FMA2(acc[2][2], ub.x, w2[2]); FMA2(acc[2][3], ub.x, w2[3]);
      FMA2(acc[3][0], ub.y, w2[0]); FMA2(acc[3][1], ub.y, w2[1]);
      FMA2(acc[3][2], ub.y, w2[2]); FMA2(acc[3][3], ub.y, w2[3]);
    }

    float cl[4], chv[4];
    if (MODE) {
      // agreement logits; v loaded lazily (L1-hot), packed over batch pair
      u64 ag[4] = {0ull, 0ull, 0ull, 0ull};
#pragma unroll
      for (int k = 0; k < 4; k++) {
        const float* vp0 = g_vsum + (size_t)(bca + 2 * k) * kOE + o * kE + eg * 4;
        float4 va = *(const float4*)vp0;
        float4 vb = *(const float4*)(vp0 + kOE);
        u64 vp;
        PACK2(vp, va.x, vb.x); FMA2(ag[k], acc[k][0], vp);
        PACK2(vp, va.y, vb.y); FMA2(ag[k], acc[k][1], vp);
        PACK2(vp, va.z, vb.z); FMA2(ag[k], acc[k][2], vp);
        PACK2(vp, va.w, vb.w); FMA2(ag[k], acc[k][3], vp);
      }
      float al[4], ah[4];
#pragma unroll
      for (int k = 0; k < 4; k++) {
        UNPK2(al[k], ah[k], ag[k]);
        al[k] += __shfl_xor_sync(0xffffffffu, al[k], 8);
        al[k] += __shfl_xor_sync(0xffffffffu, al[k], 16);
        ah[k] += __shfl_xor_sync(0xffffffffu, ah[k], 8);
        ah[k] += __shfl_xor_sync(0xffffffffu, ah[k], 16);
      }
      if (eg == 0) {
        float* ar = ab + nl * kAPad + o;
#pragma unroll
        for (int k = 0; k < 4; k++) {
          ar[(2 * k) * kO]     = al[k];
          ar[(2 * k + 1) * kO] = ah[k];
        }
      }
      __syncthreads();
      if (tid < 64) {  // softmax over o for each (nl, b-of-chunk)
        float* row = ab + (tid & 7) * kAPad + (tid >> 3) * kO;
        float m = row[0];
#pragma unroll
        for (int i = 1; i < kO; i++) m = fmaxf(m, row[i]);
        float e[kO]; float ss = 0.f;
#pragma unroll
        for (int i = 0; i < kO; i++) { e[i] = __expf(row[i] - m); ss += e[i]; }
        float inv = 1.f / ss;
#pragma unroll
        for (int i = 0; i < kO; i++) row[i] = e[i] * inv;
      }
      __syncthreads();
      const float* ar = ab + nl * kAPad + o;
#pragma unroll
      for (int k = 0; k < 4; k++) {
        cl[k]  = ar[(2 * k) * kO];
        chv[k] = ar[(2 * k + 1) * kO];
      }
    }

    // ---- weight by c ----
    u64 v16[16];
#pragma unroll
    for (int k = 0; k < 4; k++) {
      u64 cp;
      if (MODE) { PACK2(cp, cl[k], chv[k]); }
      else      { PACK2(cp, 0.1f, 0.1f); }
#pragma unroll
      for (int j = 0; j < 4; j++) MUL2(v16[k * 4 + j], acc[k][j], cp);
    }

    // ---- reduce-scatter over nl (lane bits 0-2): 14 u64 shfl ----
    u64 v8[8];
    {
      const bool sel = (nl >> 2) & 1;
#pragma unroll
      for (int i = 0; i < 8; i++) {
        u64 send = sel ? v16[i] : v16[8 + i];
        u64 recv = __shfl_xor_sync(0xffffffffu, send, 4);
        u64 keep = sel ? v16[8 + i] : v16[i];
        ADD2(v8[i], keep, recv);
      }
    }
    u64 v4[4];
    {
      const bool sel = (nl >> 1) & 1;
#pragma unroll
      for (int i = 0; i < 4; i++) {
        u64 send = sel ? v8[i] : v8[4 + i];
        u64 recv = __shfl_xor_sync(0xffffffffu, send, 2);
        u64 keep = sel ? v8[4 + i] : v8[i];
        ADD2(v4[i], keep, recv);
      }
    }
    u64 v2[2];
    {
      const bool sel = nl & 1;
#pragma unroll
      for (int i = 0; i < 2; i++) {
        u64 send = sel ? v4[i] : v4[2 + i];
        u64 recv = __shfl_xor_sync(0xffffffffu, send, 1);
        u64 keep = sel ? v4[2 + i] : v4[i];
        ADD2(v2[i], keep, recv);
      }
    }

    // lane holds m = mm, mm+1: batch-pair kk, e-offsets j0, j0+1
    {
      float l0, h0, l1, h1;
      UNPK2(l0, h0, v2[0]); UNPK2(l1, h1, v2[1]);
      float* dp = &g_part[((size_t)blockIdx.x * kB + bca + 2 * kk) * kOE
                          + o * kE + eg * 4 + j0];
      *(float2*)dp         = make_float2(l0, l1);
      *(float2*)(dp + kOE) = make_float2(h0, h1);
    }
  }
}

// Reduce 144 partials + squash. 10240 threads: (b,o) x e-quarter; n2 via shfl.
__global__ void squash_kernel(float* __restrict__ out, int mode) {
  int gt = blockIdx.x * blockDim.x + threadIdx.x;
  if (gt >= kB * kO * 4) return;
  int eq = gt & 3, row = gt >> 2;      // row = b*10 + o
  const float* pp = g_part + (size_t)row * kE + eq * 4;
  float4 a = {0.f, 0.f, 0.f, 0.f};
#pragma unroll 4
  for (int p = 0; p < kGX; p++) {
    float4 t = *(const float4*)(pp + (size_t)p * kB * kOE);
    a.x += t.x; a.y += t.y; a.z += t.z; a.w += t.w;
  }
  float n2 = a.x * a.x + a.y * a.y + a.z * a.z + a.w * a.w;
  n2 += __shfl_xor_sync(0xffffffffu, n2, 1);
  n2 += __shfl_xor_sync(0xffffffffu, n2, 2);
  float f = sqrtf(n2) / (1.f + n2);
  float4 v = make_float4(a.x * f, a.y * f, a.z * f, a.w * f);
  if (mode == 2) {
    *(float4*)(out + (size_t)row * kE + eq * 4) = v;
  } else if (mode == 1) {
    float4 old = *(const float4*)(g_vsum + (size_t)row * kE + eq * 4);
    v.x += old.x; v.y += old.y; v.z += old.z; v.w += old.w;
    *(float4*)(g_vsum + (size_t)row * kE + eq * 4) = v;
  } else {
    *(float4*)(g_vsum + (size_t)row * kE + eq * 4) = v;
  }
}

extern "C" void kernel_launch(void* const* d_in, const int* in_sizes, int n_in,
                              void* d_out, int out_size) {
  const float* u    = (const float*)d_in[0];
  const float* W    = (const float*)d_in[1];
  const float* bias = (const float*)d_in[2];
  float* out = (float*)d_out;

  cudaFuncSetAttribute((const void*)pass_kernel<0>,
                       cudaFuncAttributeMaxDynamicSharedMemorySize, kSmemBytes);
  cudaFuncSetAttribute((const void*)pass_kernel<1>,
                       cudaFuncAttributeMaxDynamicSharedMemorySize, kSmemBytes);

  dim3 grid(kGX, kGY);  // 144 x 2 = 288 blocks, 2 CTAs/SM

  noop_kernel<<<1, 32>>>();  // keeps ncu -s 5 -c 1 on the 2nd pass_kernel<1>

  pass_kernel<0><<<grid, kTH, kSmemBytes>>>(u, W, bias);
  squash_kernel<<<40, 256>>>(nullptr, 0);

  pass_kernel<1><<<grid, kTH, kSmemBytes>>>(u, W, bias);
  squash_kernel<<<40, 256>>>(nullptr, 1);

  pass_kernel<1><<<grid, kTH, kSmemBytes>>>(u, W, bias);
  squash_kernel<<<40, 256>>>(out, 2);
}

// round 6
// speedup vs baseline: 1.0111x; 1.0111x over previous
#include <cuda_runtime.h>
#include <math.h>

// Problem constants
constexpr int kB = 256, kN = 1152, kD = 8, kO = 10, kE = 16;
constexpr int kOE = kO * kE;  // 160

// Tiling: block owns 8 n and half the batches (128), in 16 chunks of 8.
constexpr int kNL   = 8;
constexpr int kTH   = 320;        // tid = nl + 8*eg + 32*o  (warp == o)
constexpr int kGX   = kN / kNL;   // 144 n-groups
constexpr int kGY   = 2;          // batch halves
constexpr int kBH   = kB / kGY;   // 128
constexpr int kCB   = 8;
constexpr int kNCH  = kBH / kCB;  // 16

// SMEM (floats)
constexpr int kUSd  = kBH;                  // u_s d stride (128)
constexpr int kUSnl = kD * kUSd + 4;        // 1028 (nl tiles banks by 4)
constexpr int kOffL = kNL * kUSnl;          // 8224 : logits [nl][b128][o10]
constexpr int kLSnl = kBH * kO + 4;         // 1284 (nl bank offset 4: conflict-free)
constexpr int kSmemFloats1 = kOffL + kNL * kLSnl;  // 18496 (MODE 1)
constexpr int kSmemBytes1  = kSmemFloats1 * 4;     // 73984
constexpr int kSmemBytes0  = kOffL * 4;            // 32896 (MODE 0)

typedef unsigned long long u64;

__device__ float g_part[(size_t)kGX * kB * kOE];  // 23.6 MB
__device__ float g_vsum[kB * kOE];

#define FMA2(d, a, b_) asm("fma.rn.f32x2 %0, %1, %2, %0;" : "+l"(d) : "l"(a), "l"(b_))
#define MUL2(d, a, b_) asm("mul.rn.f32x2 %0, %1, %2;" : "=l"(d) : "l"(a), "l"(b_))
#define ADD2(d, a, b_) asm("add.rn.f32x2 %0, %1, %2;" : "=l"(d) : "l"(a), "l"(b_))
#define PACK2(d, lo, hi) \
  asm("mov.b64 %0, {%1, %2};" : "=l"(d) : "r"(__float_as_uint(lo)), "r"(__float_as_uint(hi)))
#define UNPK2(lo, hi, v)                                                \
  do {                                                                  \
    unsigned _l, _h;                                                    \
    asm("mov.b64 {%0, %1}, %2;" : "=r"(_l), "=r"(_h) : "l"(v));         \
    lo = __uint_as_float(_l); hi = __uint_as_float(_h);                 \
  } while (0)

__global__ void noop_kernel() {}

// Compute the 4x4 u_ji accumulator tile (bias included) for one chunk.
__device__ __forceinline__ void compute_acc(
    u64 acc[4][4], const float* __restrict__ up, const float w[kD][4], u64 bp)
{
#pragma unroll
  for (int k = 0; k < 4; k++)
#pragma unroll
    for (int j = 0; j < 4; j++) acc[k][j] = bp;
#pragma unroll
  for (int d = 0; d < kD; d++) {
    ulonglong2 ua = *(const ulonglong2*)(up + d * kUSd);      // b (0,1),(2,3)
    ulonglong2 ub = *(const ulonglong2*)(up + d * kUSd + 4);  // b (4,5),(6,7)
    u64 w2[4];
    PACK2(w2[0], w[d][0], w[d][0]); PACK2(w2[1], w[d][1], w[d][1]);
    PACK2(w2[2], w[d][2], w[d][2]); PACK2(w2[3], w[d][3], w[d][3]);
    FMA2(acc[0][0], ua.x, w2[0]); FMA2(acc[0][1], ua.x, w2[1]);
    FMA2(acc[0][2], ua.x, w2[2]); FMA2(acc[0][3], ua.x, w2[3]);
    FMA2(acc[1][0], ua.y, w2[0]); FMA2(acc[1][1], ua.y, w2[1]);
    FMA2(acc[1][2], ua.y, w2[2]); FMA2(acc[1][3], ua.y, w2[3]);
    FMA2(acc[2][0], ub.x, w2[0]); FMA2(acc[2][1], ub.x, w2[1]);
    FMA2(acc[2][2], ub.x, w2[2]); FMA2(acc[2][3], ub.x, w2[3]);
    FMA2(acc[3][0], ub.y, w2[0]); FMA2(acc[3][1], ub.y, w2[1]);
    FMA2(acc[3][2], ub.y, w2[2]); FMA2(acc[3][3], ub.y, w2[3]);
  }
}

// MODE 0: c = 0.1 folded into squash scale.  MODE 1: c = softmax_o(<u_ji, g_vsum>).
template <int MODE>
__global__ void __launch_bounds__(kTH, 2) pass_kernel(
    const float* __restrict__ u_i,
    const float* __restrict__ W,
    const float* __restrict__ bias)
{
  extern __shared__ float sm[];
  float* u_s = sm;             // [nl(1028)][d(128)][b]
  float* l_s = sm + kOffL;     // [nl(1284)][b][o]  (MODE 1 only)

  const int tid = threadIdx.x;
  const int nl  = tid & 7;
  const int eg  = (tid >> 3) & 3;
  const int o   = tid >> 5;
  const int n0  = blockIdx.x * kNL;
  const int bb0 = blockIdx.y * kBH;

  // ---- W slice + bias into registers ----
  float w[kD][4];
  {
    const float* Wp = W + ((size_t)(n0 + nl) * kO + o) * (kD * kE) + eg * 4;
#pragma unroll
    for (int d = 0; d < kD; d++) {
      float4 w4 = *(const float4*)(Wp + d * kE);
      w[d][0] = w4.x; w[d][1] = w4.y; w[d][2] = w4.z; w[d][3] = w4.w;
    }
  }
  const float bv = bias[(n0 + nl) * kO + o];
  u64 bp; PACK2(bp, bv, bv);

  // ---- stage u once: [b][n][d] -> [nl][d][b_local] ----
  for (int i = tid; i < kBH * kNL * 2; i += kTH) {
    int b = i >> 4, nl2 = (i >> 1) & 7, h = i & 1;
    float4 t = *(const float4*)(u_i + ((size_t)(bb0 + b) * kN + n0 + nl2) * kD + h * 4);
    float* du = u_s + nl2 * kUSnl + h * 4 * kUSd + b;
    du[0] = t.x; du[kUSd] = t.y; du[2 * kUSd] = t.z; du[3 * kUSd] = t.w;
  }
  __syncthreads();

  const float* up_base = u_s + nl * kUSnl;
  const int mm = ((nl >> 2) & 1) * 8 + ((nl >> 1) & 1) * 4 + (nl & 1) * 2;
  const int kk = mm >> 2, j0 = mm & 3;

  if (MODE) {
    // ===== Phase A: logits for ALL chunks (no barriers inside) =====
    for (int ch = 0; ch < kNCH; ch++) {
      const int bc  = ch * kCB;
      const int bca = bb0 + bc;
      u64 acc[4][4];
      compute_acc(acc, up_base + bc, w, bp);

      u64 ag[4] = {0ull, 0ull, 0ull, 0ull};
#pragma unroll
      for (int k = 0; k < 4; k++) {
        const float* vp0 = g_vsum + (size_t)(bca + 2 * k) * kOE + o * kE + eg * 4;
        float4 va = *(const float4*)vp0;
        float4 vb = *(const float4*)(vp0 + kOE);
        u64 vp;
        PACK2(vp, va.x, vb.x); FMA2(ag[k], acc[k][0], vp);
        PACK2(vp, va.y, vb.y); FMA2(ag[k], acc[k][1], vp);
        PACK2(vp, va.z, vb.z); FMA2(ag[k], acc[k][2], vp);
        PACK2(vp, va.w, vb.w); FMA2(ag[k], acc[k][3], vp);
      }
      float al[4], ah[4];
#pragma unroll
      for (int k = 0; k < 4; k++) {
        UNPK2(al[k], ah[k], ag[k]);
        al[k] += __shfl_xor_sync(0xffffffffu, al[k], 8);
        al[k] += __shfl_xor_sync(0xffffffffu, al[k], 16);
        ah[k] += __shfl_xor_sync(0xffffffffu, ah[k], 8);
        ah[k] += __shfl_xor_sync(0xffffffffu, ah[k], 16);
      }
      if (eg == 0) {
        float* ar = l_s + nl * kLSnl + bc * kO + o;
#pragma unroll
        for (int k = 0; k < 4; k++) {
          ar[(2 * k) * kO]     = al[k];
          ar[(2 * k + 1) * kO] = ah[k];
        }
      }
    }
    __syncthreads();

    // ===== Phase B: softmax over o for all 1024 (nl, b) rows in parallel =====
    for (int r = tid; r < kNL * kBH; r += kTH) {
      float* row = l_s + (r >> 7) * kLSnl + (r & 127) * kO;
      float m = row[0];
#pragma unroll
      for (int i = 1; i < kO; i++) m = fmaxf(m, row[i]);
      float e[kO]; float ss = 0.f;
#pragma unroll
      for (int i = 0; i < kO; i++) { e[i] = __expf(row[i] - m); ss += e[i]; }
      float inv = 1.f / ss;
#pragma unroll
      for (int i = 0; i < kO; i++) row[i] = e[i] * inv;
    }
    __syncthreads();
  }

  // ===== Phase C: weighted sum, nl reduce-scatter, store partials =====
  for (int ch = 0; ch < kNCH; ch++) {
    const int bc  = ch * kCB;
    const int bca = bb0 + bc;
    u64 acc[4][4];
    compute_acc(acc, up_base + bc, w, bp);

    u64 v16[16];
    if (MODE) {
      const float* cr = l_s + nl * kLSnl + bc * kO + o;
#pragma unroll
      for (int k = 0; k < 4; k++) {
        u64 cp; PACK2(cp, cr[(2 * k) * kO], cr[(2 * k + 1) * kO]);
#pragma unroll
        for (int j = 0; j < 4; j++) MUL2(v16[k * 4 + j], acc[k][j], cp);
      }
    } else {
      // c uniform: emit raw sums; 0.1 folded into squash scale
#pragma unroll
      for (int k = 0; k < 4; k++)
#pragma unroll
        for (int j = 0; j < 4; j++) v16[k * 4 + j] = acc[k][j];
    }

    // reduce-scatter over nl (lane bits 0-2)
    u64 v8[8];
    {
      const bool sel = (nl >> 2) & 1;
#pragma unroll
      for (int i = 0; i < 8; i++) {
        u64 send = sel ? v16[i] : v16[8 + i];
        u64 recv = __shfl_xor_sync(0xffffffffu, send, 4);
        u64 keep = sel ? v16[8 + i] : v16[i];
        ADD2(v8[i], keep, recv);
      }
    }
    u64 v4[4];
    {
      const bool sel = (nl >> 1) & 1;
#pragma unroll
      for (int i = 0; i < 4; i++) {
        u64 send = sel ? v8[i] : v8[4 + i];
        u64 recv = __shfl_xor_sync(0xffffffffu, send, 2);
        u64 keep = sel ? v8[4 + i] : v8[i];
        ADD2(v4[i], keep, recv);
      }
    }
    u64 v2[2];
    {
      const bool sel = nl & 1;
#pragma unroll
      for (int i = 0; i < 2; i++) {
        u64 send = sel ? v4[i] : v4[2 + i];
        u64 recv = __shfl_xor_sync(0xffffffffu, send, 1);
        u64 keep = sel ? v4[2 + i] : v4[i];
        ADD2(v2[i], keep, recv);
      }
    }
    {
      float l0, h0, l1, h1;
      UNPK2(l0, h0, v2[0]); UNPK2(l1, h1, v2[1]);
      float* dp = &g_part[((size_t)blockIdx.x * kB + bca + 2 * kk) * kOE
                          + o * kE + eg * 4 + j0];
      *(float2*)dp         = make_float2(l0, l1);
      *(float2*)(dp + kOE) = make_float2(h0, h1);
    }
  }
}

// Reduce 144 partials (scaled) + squash; mode 0: vsum=v, 1: vsum+=v, 2: out=v.
__global__ void squash_kernel(float* __restrict__ out, int mode, float scale) {
  int gt = blockIdx.x * blockDim.x + threadIdx.x;
  if (gt >= kB * kO * 4) return;
  int eq = gt & 3, row = gt >> 2;
  const float* pp = g_part + (size_t)row * kE + eq * 4;
  float4 a = {0.f, 0.f, 0.f, 0.f};
#pragma unroll 4
  for (int p = 0; p < kGX; p++) {
    float4 t = *(const float4*)(pp + (size_t)p * kB * kOE);
    a.x += t.x; a.y += t.y; a.z += t.z; a.w += t.w;
  }
  a.x *= scale; a.y *= scale; a.z *= scale; a.w *= scale;
  float n2 = a.x * a.x + a.y * a.y + a.z * a.z + a.w * a.w;
  n2 += __shfl_xor_sync(0xffffffffu, n2, 1);
  n2 += __shfl_xor_sync(0xffffffffu, n2, 2);
  float f = sqrtf(n2) / (1.f + n2);
  float4 v = make_float4(a.x * f, a.y * f, a.z * f, a.w * f);
  if (mode == 2) {
    *(float4*)(out + (size_t)row * kE + eq * 4) = v;
  } else if (mode == 1) {
    float4 old = *(const float4*)(g_vsum + (size_t)row * kE + eq * 4);
    v.x += old.x; v.y += old.y; v.z += old.z; v.w += old.w;
    *(float4*)(g_vsum + (size_t)row * kE + eq * 4) = v;
  } else {
    *(float4*)(g_vsum + (size_t)row * kE + eq * 4) = v;
  }
}

extern "C" void kernel_launch(void* const* d_in, const int* in_sizes, int n_in,
                              void* d_out, int out_size) {
  const float* u    = (const float*)d_in[0];
  const float* W    = (const float*)d_in[1];
  const float* bias = (const float*)d_in[2];
  float* out = (float*)d_out;

  cudaFuncSetAttribute((const void*)pass_kernel<0>,
                       cudaFuncAttributeMaxDynamicSharedMemorySize, kSmemBytes0);
  cudaFuncSetAttribute((const void*)pass_kernel<1>,
                       cudaFuncAttributeMaxDynamicSharedMemorySize, kSmemBytes1);

  dim3 grid(kGX, kGY);  // 288 blocks, 2 CTAs/SM

  noop_kernel<<<1, 32>>>();  // keeps ncu -s 5 -c 1 on the 2nd pass_kernel<1>

  pass_kernel<0><<<grid, kTH, kSmemBytes0>>>(u, W, bias);
  squash_kernel<<<40, 256>>>(nullptr, 0, 0.1f);

  pass_kernel<1><<<grid, kTH, kSmemBytes1>>>(u, W, bias);
  squash_kernel<<<40, 256>>>(nullptr, 1, 1.0f);

  pass_kernel<1><<<grid, kTH, kSmemBytes1>>>(u, W, bias);
  squash_kernel<<<40, 256>>>(out, 2, 1.0f);
}